// round 15
// baseline (speedup 1.0000x reference)
#include <cuda_runtime.h>
#include <cuda_fp16.h>
#include <cstdint>
#include <math.h>

// LSTM B=128, S=256, I=1024, H=1024. out[b,s,h] fp32.
// FUSED persistent scan: gates = [h_t | x_t] @ W^T + b per step (K=2048).
// Phase 0: pack x to fp16. Scan: 128 CTAs x 256 thr; 4 pairs (mg) x 2 k-warps
// (km); pair-private DOUBLE-buffered cp.async staging; 16 chunks of 128 cols.

#define NBLK2 128
#define WS3_STRIDE 1028              // 1024 + 4 pad (u32); row = 2048 fp16
#define ST3_STRIDE 68                // 64 + 4 pad (u32); 272B row, 16B-aligned
#define PAIR_SLAB3 (2 * 32 * ST3_STRIDE)                  // u32 (2 buffers)
#define RED3_OFF   (32 * WS3_STRIDE + 4 * PAIR_SLAB3)     // u32 offset
#define SMEM3_BYTES ((RED3_OFF + 128 * 33) * 4)           // 218,112 B

__device__ __align__(16) __half   g_h[2 * 128 * 1024];             // h fp16, dbl buf
__device__ __align__(16) __half   g_xh[(size_t)128 * 256 * 1024];  // x fp16 (64 MB)
__device__ unsigned g_arrive = 0;

__device__ __forceinline__ uint32_t packh2(float a, float b) {
    __half2 h = __floats2half2_rn(a, b);
    return *reinterpret_cast<uint32_t*>(&h);
}

__device__ __forceinline__ void mma_f16(float d[4], const uint32_t a[4], const uint32_t b[2]) {
    asm volatile(
        "mma.sync.aligned.m16n8k16.row.col.f32.f16.f16.f32 "
        "{%0,%1,%2,%3},{%4,%5,%6,%7},{%8,%9},{%0,%1,%2,%3};"
        : "+f"(d[0]), "+f"(d[1]), "+f"(d[2]), "+f"(d[3])
        : "r"(a[0]), "r"(a[1]), "r"(a[2]), "r"(a[3]), "r"(b[0]), "r"(b[1]));
}

__device__ __forceinline__ float sigm(float x) { return 1.0f / (1.0f + expf(-x)); }

// ---------------------------------------------------------------------------
// Phase 0: pack x fp32 -> fp16 (layout preserved: [b][s][k])
// ---------------------------------------------------------------------------
__global__ __launch_bounds__(256) void pack_x_kernel(const float* __restrict__ x) {
    size_t i4 = (size_t)blockIdx.x * 256 + threadIdx.x;   // float4 index
    float4 v = reinterpret_cast<const float4*>(x)[i4];
    uint2 o;
    o.x = packh2(v.x, v.y);
    o.y = packh2(v.z, v.w);
    reinterpret_cast<uint2*>(g_xh)[i4] = o;
}

// ---------------------------------------------------------------------------
// Fused persistent scan
// ---------------------------------------------------------------------------
__device__ __forceinline__ void grid_barrier() {
    __threadfence();
    __syncthreads();
    if (threadIdx.x == 0) {
        unsigned old = atomicAdd(&g_arrive, 1u);
        unsigned target = (old / gridDim.x + 1u) * gridDim.x;
        while (*(volatile unsigned*)&g_arrive < target) {
            __nanosleep(32);
        }
        __threadfence();
    }
    __syncthreads();
}

__global__ void __launch_bounds__(256, 1) lstm_scan_kernel(
    const float* __restrict__ Wf, const float* __restrict__ bf,
    const float* __restrict__ Wi, const float* __restrict__ bi,
    const float* __restrict__ Wc, const float* __restrict__ bc,
    const float* __restrict__ Wo, const float* __restrict__ bo,
    float* __restrict__ out)
{
    extern __shared__ uint8_t smem[];
    uint32_t* Ws  = reinterpret_cast<uint32_t*>(smem);                   // [32][WS3_STRIDE]
    uint32_t* Stg = reinterpret_cast<uint32_t*>(smem) + 32 * WS3_STRIDE; // [4][2][32][ST3_STRIDE]
    float*    red = reinterpret_cast<float*>(smem) + RED3_OFF;           // [128][33]

    const float* Wsel[4] = {Wf, Wi, Wc, Wo};
    const float* bsel[4] = {bf, bi, bc, bo};
    const int tid  = threadIdx.x;
    const int warp = tid >> 5;
    const int lane = tid & 31;
    const int q = lane >> 2, p = lane & 3;
    const int mg = warp & 3;     // pair id (32 batches)
    const int km = warp >> 2;    // member in pair (k-interleave)
    const int j0 = blockIdx.x * 8;

    uint32_t* slab = Stg + mg * PAIR_SLAB3;
    const uint32_t slab_base = (uint32_t)__cvta_generic_to_shared(slab);
    const uint32_t* __restrict__ xh32 = reinterpret_cast<const uint32_t*>(g_xh);

    // Load full W slice (rows j0..j0+7 per gate, 2048 cols: [Wh | Wx]) as fp16
    for (int idx = tid; idx < 32 * 512; idx += 256) {
        int cc = idx >> 9;               // row 0..31 (gate*8 + jj)
        int k4 = (idx & 511) * 4;        // fp32 col
        int g = cc >> 3, jj = cc & 7;
        const float* Wg = Wsel[g];
        float4 v = *reinterpret_cast<const float4*>(&Wg[(size_t)(j0 + jj) * 2048 + k4]);
        uint32_t* wr = &Ws[cc * WS3_STRIDE + (k4 >> 1)];
        wr[0] = packh2(v.x, v.y);
        wr[1] = packh2(v.z, v.w);
    }
    for (int idx = tid; idx < 1024; idx += 256) {
        int b = idx >> 3, jj = idx & 7;
        g_h[b * 1024 + j0 + jj] = __float2half_rn(0.0f);
    }
    // bias preload: this thread's 2 columns (jj = 2p, 2p+1) per gate
    float bs[4][2];
    #pragma unroll
    for (int g = 0; g < 4; ++g) {
        bs[g][0] = bsel[g][j0 + 2 * p];
        bs[g][1] = bsel[g][j0 + 2 * p + 1];
    }
    float cst[8];
    #pragma unroll
    for (int i = 0; i < 8; ++i) cst[i] = 0.0f;

    // staging map: pair copies 32 rows x 64 u32 (256B) per chunk; 64 thr x 8 ops
    const int tid64 = km * 32 + lane;
    int srow[8], sseg[8];
    uint32_t dsm_off[8];
    #pragma unroll
    for (int it = 0; it < 8; ++it) {
        int idx = tid64 + 64 * it;       // 0..511
        srow[it] = idx >> 4;             // 0..31 (16 x 16B ops per row)
        sseg[it] = (idx & 15) * 4;       // u32 col in chunk (0..60)
        dsm_off[it] = (uint32_t)((srow[it] * ST3_STRIDE + sseg[it]) << 2);
    }

    grid_barrier();

    for (int t = 0; t < 256; ++t) {
        const uint32_t* __restrict__ hin =
            reinterpret_cast<const uint32_t*>(&g_h[(t & 1) * (128 * 1024)]);
        __half* __restrict__ hout = &g_h[((t + 1) & 1) * (128 * 1024)];

        // hoisted per-thread source base pointers (h side / x side)
        const uint32_t* hb[8];
        const uint32_t* xb[8];
        #pragma unroll
        for (int it = 0; it < 8; ++it) {
            int row = mg * 32 + srow[it];
            hb[it] = hin + (size_t)row * 512 + sseg[it];
            xb[it] = xh32 + ((size_t)row * 256 + t) * 512 + sseg[it];
        }

        float acc[2][4][4];
        #pragma unroll
        for (int mt = 0; mt < 2; ++mt)
            #pragma unroll
            for (int nt = 0; nt < 4; ++nt)
                #pragma unroll
                for (int r = 0; r < 4; ++r) acc[mt][nt][r] = 0.0f;

        // prologue: issue chunk 0 into buf 0
        #pragma unroll
        for (int it = 0; it < 8; ++it) {
            uint32_t dsm = slab_base + dsm_off[it];
            asm volatile("cp.async.cg.shared.global [%0], [%1], 16;"
                         :: "r"(dsm), "l"(hb[it]));
        }
        asm volatile("cp.async.commit_group;");

        for (int c = 0; c < 16; ++c) {
            asm volatile("cp.async.wait_group 0;");                      // chunk c landed
            asm volatile("bar.sync %0, 64;" :: "r"(1 + mg) : "memory");  // pair barrier

            if (c < 15) {    // issue c+1 into other buffer (consumed at c-1)
                int cc = c + 1;
                uint32_t boff = (uint32_t)((cc & 1) * 32 * ST3_STRIDE) << 2;
                #pragma unroll
                for (int it = 0; it < 8; ++it) {
                    uint32_t dsm = slab_base + boff + dsm_off[it];
                    const uint32_t* src = (cc < 8) ? (hb[it] + cc * 64)
                                                   : (xb[it] + (cc - 8) * 64);
                    asm volatile("cp.async.cg.shared.global [%0], [%1], 16;"
                                 :: "r"(dsm), "l"(src));
                }
                asm volatile("cp.async.commit_group;");
            }

            const uint32_t* Ab = slab + (c & 1) * (32 * ST3_STRIDE);
            #pragma unroll
            for (int s = 0; s < 4; ++s) {
                const int fi = 2 * s + km;              // k16 frag in chunk (0..7)
                const int au = fi * 8 + p;              // u32 col in staging row
                const int bu = c * 64 + fi * 8 + p;     // u32 col in Ws row
                uint32_t a[2][4];
                #pragma unroll
                for (int mt = 0; mt < 2; ++mt) {
                    int rb = mt * 16 + q;
                    a[mt][0] = Ab[rb * ST3_STRIDE + au];
                    a[mt][1] = Ab[(rb + 8) * ST3_STRIDE + au];
                    a[mt][2] = Ab[rb * ST3_STRIDE + au + 4];
                    a[mt][3] = Ab[(rb + 8) * ST3_STRIDE + au + 4];
                }
                #pragma unroll
                for (int nt = 0; nt < 4; ++nt) {
                    uint32_t bb[2];
                    int nr = nt * 8 + q;
                    bb[0] = Ws[nr * WS3_STRIDE + bu];
                    bb[1] = Ws[nr * WS3_STRIDE + bu + 4];
                    mma_f16(acc[0][nt], a[0], bb);
                    mma_f16(acc[1][nt], a[1], bb);
                }
            }
        }

        // 2-way k reduction through dedicated smem (pair-scoped)
        if (km == 1) {
            float* w = &red[(mg * 32 + lane) * 33];
            #pragma unroll
            for (int mt = 0; mt < 2; ++mt)
                #pragma unroll
                for (int nt = 0; nt < 4; ++nt)
                    #pragma unroll
                    for (int r = 0; r < 4; ++r)
                        w[mt * 16 + nt * 4 + r] = acc[mt][nt][r];
        }
        asm volatile("bar.sync %0, 64;" :: "r"(1 + mg) : "memory");
        if (km == 0) {
            const float* w = &red[(mg * 32 + lane) * 33];
            #pragma unroll
            for (int mt = 0; mt < 2; ++mt)
                #pragma unroll
                for (int nt = 0; nt < 4; ++nt)
                    #pragma unroll
                    for (int r = 0; r < 4; ++r)
                        acc[mt][nt][r] += w[mt * 16 + nt * 4 + r];

            #pragma unroll
            for (int mt = 0; mt < 2; ++mt)
                #pragma unroll
                for (int r = 0; r < 4; ++r) {
                    int rr = mt * 2 + (r >> 1);
                    int row = mg * 32 + q + rr * 8;
                    int jj = 2 * p + (r & 1);
                    int e = r & 1;
                    float fg = sigm(acc[mt][0][r] + bs[0][e]);
                    float ig = sigm(acc[mt][1][r] + bs[1][e]);
                    float gg = tanhf(acc[mt][2][r] + bs[2][e]);
                    float og = sigm(acc[mt][3][r] + bs[3][e]);
                    float cnew = cst[mt * 4 + r] * fg + ig * gg;
                    cst[mt * 4 + r] = cnew;
                    float hnew = tanhf(cnew) * og;
                    hout[row * 1024 + j0 + jj] = __float2half_rn(hnew);
                    out[(size_t)row * (256 * 1024) + t * 1024 + j0 + jj] = hnew;
                }
        }
        grid_barrier();
    }
}

// ---------------------------------------------------------------------------
extern "C" void kernel_launch(void* const* d_in, const int* in_sizes, int n_in,
                              void* d_out, int out_size) {
    const float* x  = (const float*)d_in[0];
    const float* Wf = (const float*)d_in[1];
    const float* bf = (const float*)d_in[2];
    const float* Wi = (const float*)d_in[3];
    const float* bi = (const float*)d_in[4];
    const float* Wc = (const float*)d_in[5];
    const float* bc = (const float*)d_in[6];
    const float* Wo = (const float*)d_in[7];
    const float* bo = (const float*)d_in[8];
    float* out = (float*)d_out;

    cudaFuncSetAttribute(lstm_scan_kernel,
                         cudaFuncAttributeMaxDynamicSharedMemorySize, SMEM3_BYTES);

    pack_x_kernel<<<32768, 256>>>(x);
    lstm_scan_kernel<<<NBLK2, 256, SMEM3_BYTES>>>(Wf, bf, Wi, bi, Wc, bc, Wo, bo, out);
}

// round 16
// speedup vs baseline: 1.8722x; 1.8722x over previous
#include <cuda_runtime.h>
#include <cuda_fp16.h>
#include <cstdint>
#include <math.h>

// LSTM B=128, S=256, I=1024, H=1024. out[b,s,h] fp32.
// FUSED persistent scan: gates = [h_t | x_t] @ W^T + b per step (K=2048).
// Phase 0: pack x to fp16.
// Scan: 128 CTAs x 256 thr = 8 WARP-AUTONOMOUS pipelines; each warp owns
// 16 batches x full K with private double-buffered cp.async staging
// (issue-before-wait => true overlap). No pair barriers, no reduction.

#define NBLK2 128
#define WS3_STRIDE 1028              // 1024 + 4 pad (u32); row = 2048 fp16
#define ST3_STRIDE 68                // 64 + 4 pad (u32); 272B row, 16B-aligned
#define WARP_SLAB (2 * 16 * ST3_STRIDE)                  // u32: 2 bufs x 16 rows
#define SMEM3_BYTES ((32 * WS3_STRIDE + 8 * WARP_SLAB) * 4)   // 201,216 B

__device__ __align__(16) __half   g_h[2 * 128 * 1024];             // h fp16, dbl buf
__device__ __align__(16) __half   g_xh[(size_t)128 * 256 * 1024];  // x fp16 (64 MB)
__device__ unsigned g_arrive = 0;

__device__ __forceinline__ uint32_t packh2(float a, float b) {
    __half2 h = __floats2half2_rn(a, b);
    return *reinterpret_cast<uint32_t*>(&h);
}

__device__ __forceinline__ void mma_f16(float d[4], const uint32_t a[4], const uint32_t b[2]) {
    asm volatile(
        "mma.sync.aligned.m16n8k16.row.col.f32.f16.f16.f32 "
        "{%0,%1,%2,%3},{%4,%5,%6,%7},{%8,%9},{%0,%1,%2,%3};"
        : "+f"(d[0]), "+f"(d[1]), "+f"(d[2]), "+f"(d[3])
        : "r"(a[0]), "r"(a[1]), "r"(a[2]), "r"(a[3]), "r"(b[0]), "r"(b[1]));
}

__device__ __forceinline__ float sigm(float x) { return 1.0f / (1.0f + expf(-x)); }

// ---------------------------------------------------------------------------
// Phase 0: pack x fp32 -> fp16 (layout preserved: [b][s][k])
// ---------------------------------------------------------------------------
__global__ __launch_bounds__(256) void pack_x_kernel(const float* __restrict__ x) {
    size_t i4 = (size_t)blockIdx.x * 256 + threadIdx.x;   // float4 index
    float4 v = reinterpret_cast<const float4*>(x)[i4];
    uint2 o;
    o.x = packh2(v.x, v.y);
    o.y = packh2(v.z, v.w);
    reinterpret_cast<uint2*>(g_xh)[i4] = o;
}

// ---------------------------------------------------------------------------
// Fused persistent scan
// ---------------------------------------------------------------------------
__device__ __forceinline__ void grid_barrier() {
    __threadfence();
    __syncthreads();
    if (threadIdx.x == 0) {
        unsigned old = atomicAdd(&g_arrive, 1u);
        unsigned target = (old / gridDim.x + 1u) * gridDim.x;
        while (*(volatile unsigned*)&g_arrive < target) {
            __nanosleep(32);
        }
        __threadfence();
    }
    __syncthreads();
}

__global__ void __launch_bounds__(256, 1) lstm_scan_kernel(
    const float* __restrict__ Wf, const float* __restrict__ bf,
    const float* __restrict__ Wi, const float* __restrict__ bi,
    const float* __restrict__ Wc, const float* __restrict__ bc,
    const float* __restrict__ Wo, const float* __restrict__ bo,
    float* __restrict__ out)
{
    extern __shared__ uint8_t smem[];
    uint32_t* Ws  = reinterpret_cast<uint32_t*>(smem);                   // [32][WS3_STRIDE]
    uint32_t* Stg = reinterpret_cast<uint32_t*>(smem) + 32 * WS3_STRIDE; // [8][2][16][ST3_STRIDE]

    const float* Wsel[4] = {Wf, Wi, Wc, Wo};
    const float* bsel[4] = {bf, bi, bc, bo};
    const int tid  = threadIdx.x;
    const int warp = tid >> 5;   // 0..7: owns batches warp*16..+15
    const int lane = tid & 31;
    const int q = lane >> 2, p = lane & 3;
    const int j0 = blockIdx.x * 8;

    uint32_t* slab = Stg + warp * WARP_SLAB;
    const uint32_t slab_base = (uint32_t)__cvta_generic_to_shared(slab);
    const uint32_t* __restrict__ xh32 = reinterpret_cast<const uint32_t*>(g_xh);

    // Load full W slice (rows j0..j0+7 per gate, 2048 cols: [Wh | Wx]) as fp16
    for (int idx = tid; idx < 32 * 512; idx += 256) {
        int cc = idx >> 9;               // row 0..31 (gate*8 + jj)
        int k4 = (idx & 511) * 4;        // fp32 col
        int g = cc >> 3, jj = cc & 7;
        const float* Wg = Wsel[g];
        float4 v = *reinterpret_cast<const float4*>(&Wg[(size_t)(j0 + jj) * 2048 + k4]);
        uint32_t* wr = &Ws[cc * WS3_STRIDE + (k4 >> 1)];
        wr[0] = packh2(v.x, v.y);
        wr[1] = packh2(v.z, v.w);
    }
    for (int idx = tid; idx < 1024; idx += 256) {
        int b = idx >> 3, jj = idx & 7;
        g_h[b * 1024 + j0 + jj] = __float2half_rn(0.0f);
    }
    // bias preload: this thread's 2 columns (jj = 2p, 2p+1) per gate
    float bs[4][2];
    #pragma unroll
    for (int g = 0; g < 4; ++g) {
        bs[g][0] = bsel[g][j0 + 2 * p];
        bs[g][1] = bsel[g][j0 + 2 * p + 1];
    }
    float cst[4];                        // rows q,q+8 x cols 2p,2p+1
    #pragma unroll
    for (int i = 0; i < 4; ++i) cst[i] = 0.0f;

    // staging map: warp copies 16 rows x 64 u32 (256B) per chunk; 32 thr x 8 ops
    int srow[8], sseg[8];
    uint32_t dsm_off[8];
    #pragma unroll
    for (int it = 0; it < 8; ++it) {
        int idx = lane + 32 * it;        // 0..255
        srow[it] = idx >> 4;             // 0..15 (16 x 16B ops per row)
        sseg[it] = (idx & 15) * 4;       // u32 col in chunk (0..60)
        dsm_off[it] = (uint32_t)((srow[it] * ST3_STRIDE + sseg[it]) << 2);
    }

    grid_barrier();

    for (int t = 0; t < 256; ++t) {
        const uint32_t* __restrict__ hin =
            reinterpret_cast<const uint32_t*>(&g_h[(t & 1) * (128 * 1024)]);
        __half* __restrict__ hout = &g_h[((t + 1) & 1) * (128 * 1024)];

        // hoisted per-thread source base pointers (h side / x side)
        const uint32_t* hb[8];
        const uint32_t* xb[8];
        #pragma unroll
        for (int it = 0; it < 8; ++it) {
            int row = warp * 16 + srow[it];
            hb[it] = hin + (size_t)row * 512 + sseg[it];
            xb[it] = xh32 + ((size_t)row * 256 + t) * 512 + sseg[it];
        }

        float acc[4][4];
        #pragma unroll
        for (int nt = 0; nt < 4; ++nt)
            #pragma unroll
            for (int r = 0; r < 4; ++r) acc[nt][r] = 0.0f;

        // prologue: issue chunk 0 into buf 0
        #pragma unroll
        for (int it = 0; it < 8; ++it) {
            asm volatile("cp.async.cg.shared.global [%0], [%1], 16;"
                         :: "r"(slab_base + dsm_off[it]), "l"(hb[it]));
        }
        asm volatile("cp.async.commit_group;");

        for (int c = 0; c < 16; ++c) {
            // issue c+1 FIRST (its buffer was consumed by this warp at c-1)
            if (c < 15) {
                int cc = c + 1;
                uint32_t boff = (uint32_t)((cc & 1) * 16 * ST3_STRIDE) << 2;
                #pragma unroll
                for (int it = 0; it < 8; ++it) {
                    const uint32_t* src = (cc < 8) ? (hb[it] + cc * 64)
                                                   : (xb[it] + (cc - 8) * 64);
                    asm volatile("cp.async.cg.shared.global [%0], [%1], 16;"
                                 :: "r"(slab_base + boff + dsm_off[it]), "l"(src));
                }
                asm volatile("cp.async.commit_group;");
                asm volatile("cp.async.wait_group 1;");   // chunk c landed (c+1 in flight)
            } else {
                asm volatile("cp.async.wait_group 0;");
            }
            __syncwarp();

            const uint32_t* Ab = slab + (c & 1) * (16 * ST3_STRIDE);
            #pragma unroll
            for (int fi = 0; fi < 8; ++fi) {
                const int au = fi * 8 + p;              // u32 col in staging row
                const int bu = c * 64 + fi * 8 + p;     // u32 col in Ws row
                uint32_t a[4];
                a[0] = Ab[q * ST3_STRIDE + au];
                a[1] = Ab[(q + 8) * ST3_STRIDE + au];
                a[2] = Ab[q * ST3_STRIDE + au + 4];
                a[3] = Ab[(q + 8) * ST3_STRIDE + au + 4];
                #pragma unroll
                for (int nt = 0; nt < 4; ++nt) {
                    uint32_t bb[2];
                    int nr = nt * 8 + q;
                    bb[0] = Ws[nr * WS3_STRIDE + bu];
                    bb[1] = Ws[nr * WS3_STRIDE + bu + 4];
                    mma_f16(acc[nt], a, bb);
                }
            }
            __syncwarp();   // all lanes done reading buf (c&1) before overwrite
        }

        // epilogue: every warp handles its own 16 batches (no reduction needed)
        #pragma unroll
        for (int rh = 0; rh < 2; ++rh) {            // rows q, q+8
            int row = warp * 16 + q + rh * 8;
            #pragma unroll
            for (int e = 0; e < 2; ++e) {           // cols 2p, 2p+1
                int r = rh * 2 + e;
                int jj = 2 * p + e;
                float fg = sigm(acc[0][r] + bs[0][e]);
                float ig = sigm(acc[1][r] + bs[1][e]);
                float gg = tanhf(acc[2][r] + bs[2][e]);
                float og = sigm(acc[3][r] + bs[3][e]);
                float cnew = cst[r] * fg + ig * gg;
                cst[r] = cnew;
                float hnew = tanhf(cnew) * og;
                hout[row * 1024 + j0 + jj] = __float2half_rn(hnew);
                out[(size_t)row * (256 * 1024) + t * 1024 + j0 + jj] = hnew;
            }
        }
        grid_barrier();
    }
}

// ---------------------------------------------------------------------------
extern "C" void kernel_launch(void* const* d_in, const int* in_sizes, int n_in,
                              void* d_out, int out_size) {
    const float* x  = (const float*)d_in[0];
    const float* Wf = (const float*)d_in[1];
    const float* bf = (const float*)d_in[2];
    const float* Wi = (const float*)d_in[3];
    const float* bi = (const float*)d_in[4];
    const float* Wc = (const float*)d_in[5];
    const float* bc = (const float*)d_in[6];
    const float* Wo = (const float*)d_in[7];
    const float* bo = (const float*)d_in[8];
    float* out = (float*)d_out;

    cudaFuncSetAttribute(lstm_scan_kernel,
                         cudaFuncAttributeMaxDynamicSharedMemorySize, SMEM3_BYTES);

    pack_x_kernel<<<32768, 256>>>(x);
    lstm_scan_kernel<<<NBLK2, 256, SMEM3_BYTES>>>(Wf, bf, Wi, bi, Wc, bc, Wo, bo, out);
}

// round 17
// speedup vs baseline: 1.9362x; 1.0342x over previous
#include <cuda_runtime.h>
#include <cuda_fp16.h>
#include <cstdint>
#include <math.h>

// LSTM B=128, S=256, I=1024, H=1024. out[b,s,h] fp32.
// FUSED persistent scan: gates = [h_t | x_t] @ W^T + b per step (K=2048).
// Phase 0: pack x to fp16.
// Scan: 128 CTAs x 256 thr = 8 warp-autonomous pipelines (16 batches x full K
// each), private double-buffered cp.async staging, ldmatrix fragment loads.

#define NBLK2 128
#define WS3_STRIDE 1028              // 1024 + 4 pad (u32); row = 2048 fp16
#define ST3_STRIDE 68                // 64 + 4 pad (u32); 272B row, 16B-aligned
#define WARP_SLAB (2 * 16 * ST3_STRIDE)                  // u32: 2 bufs x 16 rows
#define SMEM3_BYTES ((32 * WS3_STRIDE + 8 * WARP_SLAB) * 4)   // 201,216 B

__device__ __align__(16) __half   g_h[2 * 128 * 1024];             // h fp16, dbl buf
__device__ __align__(16) __half   g_xh[(size_t)128 * 256 * 1024];  // x fp16 (64 MB)
__device__ unsigned g_arrive = 0;

__device__ __forceinline__ uint32_t packh2(float a, float b) {
    __half2 h = __floats2half2_rn(a, b);
    return *reinterpret_cast<uint32_t*>(&h);
}

__device__ __forceinline__ void mma_f16(float d[4], const uint32_t a[4], const uint32_t b[2]) {
    asm volatile(
        "mma.sync.aligned.m16n8k16.row.col.f32.f16.f16.f32 "
        "{%0,%1,%2,%3},{%4,%5,%6,%7},{%8,%9},{%0,%1,%2,%3};"
        : "+f"(d[0]), "+f"(d[1]), "+f"(d[2]), "+f"(d[3])
        : "r"(a[0]), "r"(a[1]), "r"(a[2]), "r"(a[3]), "r"(b[0]), "r"(b[1]));
}

__device__ __forceinline__ void ldmx4(uint32_t& r0, uint32_t& r1, uint32_t& r2,
                                      uint32_t& r3, uint32_t addr) {
    asm volatile("ldmatrix.sync.aligned.m8n8.x4.shared.b16 {%0,%1,%2,%3}, [%4];"
                 : "=r"(r0), "=r"(r1), "=r"(r2), "=r"(r3) : "r"(addr));
}

__device__ __forceinline__ float sigm(float x) { return 1.0f / (1.0f + expf(-x)); }

// ---------------------------------------------------------------------------
// Phase 0: pack x fp32 -> fp16 (layout preserved: [b][s][k])
// ---------------------------------------------------------------------------
__global__ __launch_bounds__(256) void pack_x_kernel(const float* __restrict__ x) {
    size_t i4 = (size_t)blockIdx.x * 256 + threadIdx.x;   // float4 index
    float4 v = reinterpret_cast<const float4*>(x)[i4];
    uint2 o;
    o.x = packh2(v.x, v.y);
    o.y = packh2(v.z, v.w);
    reinterpret_cast<uint2*>(g_xh)[i4] = o;
}

// ---------------------------------------------------------------------------
// Fused persistent scan
// ---------------------------------------------------------------------------
__device__ __forceinline__ void grid_barrier() {
    __threadfence();
    __syncthreads();
    if (threadIdx.x == 0) {
        unsigned old = atomicAdd(&g_arrive, 1u);
        unsigned target = (old / gridDim.x + 1u) * gridDim.x;
        while (*(volatile unsigned*)&g_arrive < target) {
            __nanosleep(32);
        }
        __threadfence();
    }
    __syncthreads();
}

__global__ void __launch_bounds__(256, 1) lstm_scan_kernel(
    const float* __restrict__ Wf, const float* __restrict__ bf,
    const float* __restrict__ Wi, const float* __restrict__ bi,
    const float* __restrict__ Wc, const float* __restrict__ bc,
    const float* __restrict__ Wo, const float* __restrict__ bo,
    float* __restrict__ out)
{
    extern __shared__ uint8_t smem[];
    uint32_t* Ws  = reinterpret_cast<uint32_t*>(smem);                   // [32][WS3_STRIDE]
    uint32_t* Stg = reinterpret_cast<uint32_t*>(smem) + 32 * WS3_STRIDE; // [8][2][16][ST3_STRIDE]

    const float* Wsel[4] = {Wf, Wi, Wc, Wo};
    const float* bsel[4] = {bf, bi, bc, bo};
    const int tid  = threadIdx.x;
    const int warp = tid >> 5;   // 0..7: owns batches warp*16..+15
    const int lane = tid & 31;
    const int q = lane >> 2, p = lane & 3;
    const int j0 = blockIdx.x * 8;

    uint32_t* slab = Stg + warp * WARP_SLAB;
    const uint32_t slab_base = (uint32_t)__cvta_generic_to_shared(slab);
    const uint32_t ws_base   = (uint32_t)__cvta_generic_to_shared(Ws);
    const uint32_t* __restrict__ xh32 = reinterpret_cast<const uint32_t*>(g_xh);

    // ldmatrix per-lane address offsets (bytes)
    //  a: tiles (m0-7,kLo),(m8-15,kLo),(m0-7,kHi),(m8-15,kHi):
    //     row = lane&15, k-half = lane>>4
    const uint32_t a_lane_off = (uint32_t)(((lane & 15) * ST3_STRIDE + (lane >> 4) * 4) << 2);
    //  b: 4 tiles = gates nt0..3 (rows n=lane), k-half chosen per load
    const uint32_t b_lane_base = ws_base + (uint32_t)((lane * WS3_STRIDE) << 2);

    // Load full W slice (rows j0..j0+7 per gate, 2048 cols: [Wh | Wx]) as fp16
    for (int idx = tid; idx < 32 * 512; idx += 256) {
        int cc = idx >> 9;               // row 0..31 (gate*8 + jj)
        int k4 = (idx & 511) * 4;        // fp32 col
        int g = cc >> 3, jj = cc & 7;
        const float* Wg = Wsel[g];
        float4 v = *reinterpret_cast<const float4*>(&Wg[(size_t)(j0 + jj) * 2048 + k4]);
        uint32_t* wr = &Ws[cc * WS3_STRIDE + (k4 >> 1)];
        wr[0] = packh2(v.x, v.y);
        wr[1] = packh2(v.z, v.w);
    }
    for (int idx = tid; idx < 1024; idx += 256) {
        int b = idx >> 3, jj = idx & 7;
        g_h[b * 1024 + j0 + jj] = __float2half_rn(0.0f);
    }
    // bias preload: this thread's 2 columns (jj = 2p, 2p+1) per gate
    float bs[4][2];
    #pragma unroll
    for (int g = 0; g < 4; ++g) {
        bs[g][0] = bsel[g][j0 + 2 * p];
        bs[g][1] = bsel[g][j0 + 2 * p + 1];
    }
    float cst[4];                        // rows q,q+8 x cols 2p,2p+1
    #pragma unroll
    for (int i = 0; i < 4; ++i) cst[i] = 0.0f;

    // staging map: warp copies 16 rows x 64 u32 (256B) per chunk; 32 thr x 8 ops
    int srow[8], sseg[8];
    uint32_t dsm_off[8];
    #pragma unroll
    for (int it = 0; it < 8; ++it) {
        int idx = lane + 32 * it;        // 0..255
        srow[it] = idx >> 4;             // 0..15
        sseg[it] = (idx & 15) * 4;       // u32 col (0..60)
        dsm_off[it] = (uint32_t)((srow[it] * ST3_STRIDE + sseg[it]) << 2);
    }

    grid_barrier();

    for (int t = 0; t < 256; ++t) {
        const uint32_t* __restrict__ hin =
            reinterpret_cast<const uint32_t*>(&g_h[(t & 1) * (128 * 1024)]);
        __half* __restrict__ hout = &g_h[((t + 1) & 1) * (128 * 1024)];

        const uint32_t* hb[8];
        const uint32_t* xb[8];
        #pragma unroll
        for (int it = 0; it < 8; ++it) {
            int row = warp * 16 + srow[it];
            hb[it] = hin + (size_t)row * 512 + sseg[it];
            xb[it] = xh32 + ((size_t)row * 256 + t) * 512 + sseg[it];
        }

        float acc[4][4];
        #pragma unroll
        for (int nt = 0; nt < 4; ++nt)
            #pragma unroll
            for (int r = 0; r < 4; ++r) acc[nt][r] = 0.0f;

        // prologue: issue chunk 0 into buf 0
        #pragma unroll
        for (int it = 0; it < 8; ++it) {
            asm volatile("cp.async.cg.shared.global [%0], [%1], 16;"
                         :: "r"(slab_base + dsm_off[it]), "l"(hb[it]));
        }
        asm volatile("cp.async.commit_group;");

        for (int c = 0; c < 16; ++c) {
            // issue c+1 FIRST (its buffer was consumed by this warp at c-1)
            if (c < 15) {
                int cc = c + 1;
                uint32_t boff = (uint32_t)((cc & 1) * 16 * ST3_STRIDE) << 2;
                #pragma unroll
                for (int it = 0; it < 8; ++it) {
                    const uint32_t* src = (cc < 8) ? (hb[it] + cc * 64)
                                                   : (xb[it] + (cc - 8) * 64);
                    asm volatile("cp.async.cg.shared.global [%0], [%1], 16;"
                                 :: "r"(slab_base + boff + dsm_off[it]), "l"(src));
                }
                asm volatile("cp.async.commit_group;");
                asm volatile("cp.async.wait_group 1;");   // chunk c landed
            } else {
                asm volatile("cp.async.wait_group 0;");
            }
            __syncwarp();

            const uint32_t a_base = slab_base
                + ((uint32_t)((c & 1) * 16 * ST3_STRIDE) << 2) + a_lane_off;
            const uint32_t b_base = b_lane_base + (uint32_t)((c * 64) << 2);

            #pragma unroll
            for (int fi = 0; fi < 8; ++fi) {
                uint32_t a[4];
                ldmx4(a[0], a[1], a[2], a[3], a_base + fi * 32);
                uint32_t blo[4], bhi[4];
                ldmx4(blo[0], blo[1], blo[2], blo[3], b_base + fi * 32);
                ldmx4(bhi[0], bhi[1], bhi[2], bhi[3], b_base + fi * 32 + 16);
                #pragma unroll
                for (int nt = 0; nt < 4; ++nt) {
                    uint32_t bb[2] = { blo[nt], bhi[nt] };
                    mma_f16(acc[nt], a, bb);
                }
            }
            __syncwarp();   // all lanes done reading buf (c&1) before overwrite
        }

        // epilogue: every warp handles its own 16 batches
        #pragma unroll
        for (int rh = 0; rh < 2; ++rh) {            // rows q, q+8
            int row = warp * 16 + q + rh * 8;
            #pragma unroll
            for (int e = 0; e < 2; ++e) {           // cols 2p, 2p+1
                int r = rh * 2 + e;
                int jj = 2 * p + e;
                float fg = sigm(acc[0][r] + bs[0][e]);
                float ig = sigm(acc[1][r] + bs[1][e]);
                float gg = tanhf(acc[2][r] + bs[2][e]);
                float og = sigm(acc[3][r] + bs[3][e]);
                float cnew = cst[r] * fg + ig * gg;
                cst[r] = cnew;
                float hnew = tanhf(cnew) * og;
                hout[row * 1024 + j0 + jj] = __float2half_rn(hnew);
                out[(size_t)row * (256 * 1024) + t * 1024 + j0 + jj] = hnew;
            }
        }
        grid_barrier();
    }
}

// ---------------------------------------------------------------------------
extern "C" void kernel_launch(void* const* d_in, const int* in_sizes, int n_in,
                              void* d_out, int out_size) {
    const float* x  = (const float*)d_in[0];
    const float* Wf = (const float*)d_in[1];
    const float* bf = (const float*)d_in[2];
    const float* Wi = (const float*)d_in[3];
    const float* bi = (const float*)d_in[4];
    const float* Wc = (const float*)d_in[5];
    const float* bc = (const float*)d_in[6];
    const float* Wo = (const float*)d_in[7];
    const float* bo = (const float*)d_in[8];
    float* out = (float*)d_out;

    cudaFuncSetAttribute(lstm_scan_kernel,
                         cudaFuncAttributeMaxDynamicSharedMemorySize, SMEM3_BYTES);

    pack_x_kernel<<<32768, 256>>>(x);
    lstm_scan_kernel<<<NBLK2, 256, SMEM3_BYTES>>>(Wf, bf, Wi, bi, Wc, bc, Wo, bo, out);
}